// round 15
// baseline (speedup 1.0000x reference)
#include <cuda_runtime.h>
#include <cuda_bf16.h>
#include <cstdint>

// ---------------------------------------------------------------------------
// out[n] = (segment_sum(pred_prob[src], dst)[n] - 1)^2 * special_cost[n]
// N = 1,000,000 nodes, E = 16,000,000 edges.
//
// v15: SINGLE fused launch. Grid = edge_blocks + apply_blocks.
//  - Edge blocks (bid < eblocks): 2 edges/thread (measured-best of the
//    swept U-curve 1->137.5, 2->129.2, 4->129.3, 8->135.2), __ldg gather,
//    atomicAdd -> RED into zero-initialized __device__ scratch. On finish:
//    threadfence + bar + one release-RED on g_done.
//  - Apply blocks (tail bids, dispatched last by index-ordered block pool):
//    PRE-LOAD special_cost (read-only) before spinning, tid0 spins on an
//    acquire load of g_done with nanosleep backoff, then block computes
//    (a-1)^2*c into out and resets accum to 0. Last apply block resets the
//    counters -> deterministic across graph replays.
// Saves the inter-kernel launch gap and hides apply's cost-load latency
// inside the spin. Scatter floor ~122.5us = LSU/L1tex issue slots.
// ---------------------------------------------------------------------------

#define MAX_NODES 1000000
__device__ float g_accum[MAX_NODES];          // static zero-init
__device__ unsigned int g_done = 0;           // scatter blocks completed
__device__ unsigned int g_apply_done = 0;     // apply blocks completed

__global__ __launch_bounds__(256) void fused_kernel(
        const float* __restrict__ pred_prob,
        const int*   __restrict__ src,
        const int*   __restrict__ dst,
        const float* __restrict__ special_cost,
        float*       __restrict__ out,
        int num_edges,
        int edge_blocks,
        int apply_blocks,
        int num_nodes) {
    if ((int)blockIdx.x < edge_blocks) {
        // ---- scatter phase ----
        int i = blockIdx.x * blockDim.x + threadIdx.x;
        int base = i * 2;
        if (base + 1 < num_edges) {
            int2 s2 = *reinterpret_cast<const int2*>(src + base);
            int2 d2 = *reinterpret_cast<const int2*>(dst + base);
            float m0 = __ldg(pred_prob + s2.x);
            float m1 = __ldg(pred_prob + s2.y);
            atomicAdd(g_accum + d2.x, m0);   // return unused -> RED
            atomicAdd(g_accum + d2.y, m1);
        } else if (base < num_edges) {
            atomicAdd(g_accum + dst[base], __ldg(pred_prob + src[base]));
        }
        __threadfence();        // order this thread's REDs (all threads)
        __syncthreads();        // all block REDs fenced before signal
        if (threadIdx.x == 0) {
            asm volatile("red.release.gpu.global.add.u32 [%0], 1;"
                         :: "l"(&g_done) : "memory");
        }
        return;
    }

    // ---- apply phase (tail blocks) ----
    int ab = blockIdx.x - edge_blocks;
    int i = ab * blockDim.x + threadIdx.x;
    int base = i * 2;

    // Pre-load read-only operand while the scatter drains.
    float2 c = make_float2(0.0f, 0.0f);
    bool full = (base + 1 < num_nodes);
    if (full) {
        c = *reinterpret_cast<const float2*>(special_cost + base);
    } else if (base < num_nodes) {
        c.x = special_cost[base];
    }

    // One thread spins on the done flag; nanosleep backoff keeps the
    // issue slots free for co-resident scatter blocks.
    if (threadIdx.x == 0) {
        unsigned int v;
        for (;;) {
            asm volatile("ld.acquire.gpu.global.u32 %0, [%1];"
                         : "=r"(v) : "l"(&g_done));
            if (v == (unsigned int)edge_blocks) break;
            __nanosleep(256);
        }
    }
    __syncthreads();
    __threadfence();   // acquire ordering for all threads in the block

    if (full) {
        float2 a = *reinterpret_cast<const float2*>(g_accum + base);
        float2 r;
        float h;
        h = a.x - 1.0f; r.x = h * h * c.x;
        h = a.y - 1.0f; r.y = h * h * c.y;
        *reinterpret_cast<float2*>(out + base) = r;
        *reinterpret_cast<float2*>(g_accum + base) = make_float2(0.0f, 0.0f);
    } else if (base < num_nodes) {
        float h = g_accum[base] - 1.0f;
        out[base] = h * h * c.x;
        g_accum[base] = 0.0f;
    }

    // Last apply block resets the counters for the next (replayed) call.
    __syncthreads();
    if (threadIdx.x == 0) {
        unsigned int prev = atomicAdd(&g_apply_done, 1u);
        if (prev == (unsigned int)(apply_blocks - 1)) {
            g_done = 0;
            g_apply_done = 0;
        }
    }
}

// ---------------------------------------------------------------------------
// Fallback path (N > MAX_NODES): classic init/scatter/apply on d_out.
// ---------------------------------------------------------------------------
__global__ __launch_bounds__(256) void init_kernel(float* __restrict__ out, int n) {
    int i = blockIdx.x * blockDim.x + threadIdx.x;
    int base = i * 4;
    if (base + 3 < n) {
        *reinterpret_cast<float4*>(out + base) =
            make_float4(-1.0f, -1.0f, -1.0f, -1.0f);
    } else {
        for (int k = base; k < n; ++k) out[k] = -1.0f;
    }
}

__global__ __launch_bounds__(256) void scatter_out_kernel(
        const float* __restrict__ pred_prob,
        const int*   __restrict__ src,
        const int*   __restrict__ dst,
        float*       __restrict__ out,
        int num_edges) {
    int i = blockIdx.x * blockDim.x + threadIdx.x;
    int base = i * 2;
    if (base + 1 < num_edges) {
        int2 s2 = *reinterpret_cast<const int2*>(src + base);
        int2 d2 = *reinterpret_cast<const int2*>(dst + base);
        atomicAdd(out + d2.x, __ldg(pred_prob + s2.x));
        atomicAdd(out + d2.y, __ldg(pred_prob + s2.y));
    } else if (base < num_edges) {
        atomicAdd(out + dst[base], __ldg(pred_prob + src[base]));
    }
}

__global__ __launch_bounds__(256) void apply_inplace_kernel(
        float* __restrict__ out,
        const float* __restrict__ special_cost,
        int n) {
    int i = blockIdx.x * blockDim.x + threadIdx.x;
    int base = i * 4;
    if (base + 3 < n) {
        float4 h = *reinterpret_cast<const float4*>(out + base);
        float4 c = *reinterpret_cast<const float4*>(special_cost + base);
        h.x = h.x * h.x * c.x;
        h.y = h.y * h.y * c.y;
        h.z = h.z * h.z * c.z;
        h.w = h.w * h.w * c.w;
        *reinterpret_cast<float4*>(out + base) = h;
    } else {
        for (int k = base; k < n; ++k) {
            float h = out[k];
            out[k] = h * h * special_cost[k];
        }
    }
}

extern "C" void kernel_launch(void* const* d_in, const int* in_sizes, int n_in,
                              void* d_out, int out_size) {
    const float* pred_prob    = (const float*)d_in[0];
    const float* special_cost = (const float*)d_in[1];
    const int*   src          = (const int*)d_in[2];
    const int*   dst          = (const int*)d_in[3];
    float*       out          = (float*)d_out;

    const int N = in_sizes[0];
    const int E = in_sizes[2];

    const int threads = 256;
    int eblocks = ((E + 1) / 2 + threads - 1) / threads;

    if (N <= MAX_NODES) {
        int ablocks = ((N + 1) / 2 + threads - 1) / threads;
        fused_kernel<<<eblocks + ablocks, threads>>>(
            pred_prob, src, dst, special_cost, out, E, eblocks, ablocks, N);
    } else {
        int nblocks = ((N + 3) / 4 + threads - 1) / threads;
        init_kernel<<<nblocks, threads>>>(out, N);
        scatter_out_kernel<<<eblocks, threads>>>(pred_prob, src, dst, out, E);
        apply_inplace_kernel<<<nblocks, threads>>>(out, special_cost, N);
    }
}

// round 16
// speedup vs baseline: 1.3282x; 1.3282x over previous
#include <cuda_runtime.h>
#include <cuda_bf16.h>
#include <cstdint>

// ---------------------------------------------------------------------------
// out[n] = (segment_sum(pred_prob[src], dst)[n] - 1)^2 * special_cost[n]
// N = 1,000,000 nodes, E = 16,000,000 edges.
//
// v16 = exact revert to the best measured config (R10/v9, 129.216us).
// 2-launch pipeline (scatter -> apply+reset) on zero-initialized __device__
// scratch.
// Scatter: 2 edges/thread, 256 threads, __ldg gather, atomicAdd -> RED.
// FLOOR (confirmed by R15 profile: L2=82.7% peak, issue=5.7%): the scatter
// is LTS/L2-bandwidth bound -- 32M random 32B-sector touches + 128MB index
// stream ~= 220-240K cyc at the ~6300 B/cyc LTS cap ~= 115-125us. SM-side
// knobs cannot move it; sector traffic is irreducible for uniform-random
// 4B gather+RED. Fusion rejected (R15: spinning apply blocks steal scatter
// residency, +43us). Batching U-curve swept: 1->137.5, 2->129.2, 4->129.3,
// 8->135.2. Apply: 4 elems/thread (R10-measured best total).
// ---------------------------------------------------------------------------

#define MAX_NODES 1000000
__device__ float g_accum[MAX_NODES];   // static zero-init

__global__ __launch_bounds__(256) void scatter_accum_kernel(
        const float* __restrict__ pred_prob,
        const int*   __restrict__ src,
        const int*   __restrict__ dst,
        int num_edges) {
    int i = blockIdx.x * blockDim.x + threadIdx.x;
    int base = i * 2;
    if (base + 1 < num_edges) {
        int2 s2 = *reinterpret_cast<const int2*>(src + base);
        int2 d2 = *reinterpret_cast<const int2*>(dst + base);
        float m0 = __ldg(pred_prob + s2.x);
        float m1 = __ldg(pred_prob + s2.y);
        atomicAdd(g_accum + d2.x, m0);   // return unused -> RED
        atomicAdd(g_accum + d2.y, m1);
    } else if (base < num_edges) {
        atomicAdd(g_accum + dst[base], __ldg(pred_prob + src[base]));
    }
}

// Reads accumulated sums, computes (a-1)^2 * cost into out, and resets the
// accumulator to zero so the next (graph-replayed) call starts clean.
__global__ __launch_bounds__(256) void apply_reset_kernel(
        const float* __restrict__ special_cost,
        float*       __restrict__ out,
        int n) {
    int i = blockIdx.x * blockDim.x + threadIdx.x;
    int base = i * 4;
    if (base + 3 < n) {
        float4 a = *reinterpret_cast<const float4*>(g_accum + base);
        float4 c = *reinterpret_cast<const float4*>(special_cost + base);
        float4 r;
        float h;
        h = a.x - 1.0f; r.x = h * h * c.x;
        h = a.y - 1.0f; r.y = h * h * c.y;
        h = a.z - 1.0f; r.z = h * h * c.z;
        h = a.w - 1.0f; r.w = h * h * c.w;
        *reinterpret_cast<float4*>(out + base) = r;
        *reinterpret_cast<float4*>(g_accum + base) =
            make_float4(0.0f, 0.0f, 0.0f, 0.0f);
    } else {
        for (int k = base; k < n; ++k) {
            float h = g_accum[k] - 1.0f;
            out[k] = h * h * special_cost[k];
            g_accum[k] = 0.0f;
        }
    }
}

// Fallback path (N > MAX_NODES): classic init/scatter/apply on d_out.
__global__ __launch_bounds__(256) void init_kernel(float* __restrict__ out, int n) {
    int i = blockIdx.x * blockDim.x + threadIdx.x;
    int base = i * 4;
    if (base + 3 < n) {
        *reinterpret_cast<float4*>(out + base) =
            make_float4(-1.0f, -1.0f, -1.0f, -1.0f);
    } else {
        for (int k = base; k < n; ++k) out[k] = -1.0f;
    }
}

__global__ __launch_bounds__(256) void scatter_out_kernel(
        const float* __restrict__ pred_prob,
        const int*   __restrict__ src,
        const int*   __restrict__ dst,
        float*       __restrict__ out,
        int num_edges) {
    int i = blockIdx.x * blockDim.x + threadIdx.x;
    int base = i * 2;
    if (base + 1 < num_edges) {
        int2 s2 = *reinterpret_cast<const int2*>(src + base);
        int2 d2 = *reinterpret_cast<const int2*>(dst + base);
        atomicAdd(out + d2.x, __ldg(pred_prob + s2.x));
        atomicAdd(out + d2.y, __ldg(pred_prob + s2.y));
    } else if (base < num_edges) {
        atomicAdd(out + dst[base], __ldg(pred_prob + src[base]));
    }
}

__global__ __launch_bounds__(256) void apply_inplace_kernel(
        float* __restrict__ out,
        const float* __restrict__ special_cost,
        int n) {
    int i = blockIdx.x * blockDim.x + threadIdx.x;
    int base = i * 4;
    if (base + 3 < n) {
        float4 h = *reinterpret_cast<const float4*>(out + base);
        float4 c = *reinterpret_cast<const float4*>(special_cost + base);
        h.x = h.x * h.x * c.x;
        h.y = h.y * h.y * c.y;
        h.z = h.z * h.z * c.z;
        h.w = h.w * h.w * c.w;
        *reinterpret_cast<float4*>(out + base) = h;
    } else {
        for (int k = base; k < n; ++k) {
            float h = out[k];
            out[k] = h * h * special_cost[k];
        }
    }
}

extern "C" void kernel_launch(void* const* d_in, const int* in_sizes, int n_in,
                              void* d_out, int out_size) {
    const float* pred_prob    = (const float*)d_in[0];
    const float* special_cost = (const float*)d_in[1];
    const int*   src          = (const int*)d_in[2];
    const int*   dst          = (const int*)d_in[3];
    float*       out          = (float*)d_out;

    const int N = in_sizes[0];
    const int E = in_sizes[2];

    const int threads = 256;
    int eblocks = ((E + 1) / 2 + threads - 1) / threads;
    int nblocks = ((N + 3) / 4 + threads - 1) / threads;

    if (N <= MAX_NODES) {
        scatter_accum_kernel<<<eblocks, threads>>>(pred_prob, src, dst, E);
        apply_reset_kernel<<<nblocks, threads>>>(special_cost, out, N);
    } else {
        init_kernel<<<nblocks, threads>>>(out, N);
        scatter_out_kernel<<<eblocks, threads>>>(pred_prob, src, dst, out, E);
        apply_inplace_kernel<<<nblocks, threads>>>(out, special_cost, N);
    }
}